// round 17
// baseline (speedup 1.0000x reference)
#include <cuda_runtime.h>
#include <cuda_bf16.h>
#include <math.h>
#include <stdint.h>

// Laplace diagonal recurrence:
//   out[t, i, f] = e[i] * out[t-1, i, f] + decay[i] * inp[t, f]
// T = 2048, N_S = 108, F = 256, fp32.
//
// R17 = R16 (59.4us, 256-bit ld/st broke the wavefront-count wall) with
// doubled concurrency: CHUNK 128->64 => grid 9x32 = 288 blocks = 2 blocks/SM
// (8 warps/SM), __launch_bounds__(128,2). All else identical: lane=tid&31
// covers a 1KB row in 32B pieces, iq=tid>>5 (KI=3 float8 states, GI=12),
// per-ib warm table, PF=8 register pipeline, f32x2 math,
// ld.global.nc.L2::evict_last.v4.b64 input, st.global.cs.v4.b64 stores.

constexpr int T_LEN  = 2048;
constexpr int F      = 256;
constexpr int NS     = 108;
constexpr int CHUNK  = 64;
constexpr int NCHUNK = T_LEN / CHUNK;   // 32
constexpr int KI     = 3;               // i-states per thread (float8 each)
constexpr int GI     = 12;              // i-values per block
constexpr int NIB    = NS / GI;         // 9
constexpr int PF     = 8;               // prefetch depth (rows)
constexpr int ROWB   = F * 4;           // 1024 bytes per (t) row per i

__device__ __constant__ int WTAB[NIB] = {8, 8, 8, 16, 16, 24, 32, 40, 56};

typedef unsigned long long u64;

__device__ __forceinline__ u64 fma2(u64 a, u64 b, u64 c) {
    u64 d;
    asm("fma.rn.f32x2 %0, %1, %2, %3;" : "=l"(d) : "l"(a), "l"(b), "l"(c));
    return d;
}
__device__ __forceinline__ u64 mul2(u64 a, u64 b) {
    u64 d;
    asm("mul.rn.f32x2 %0, %1, %2;" : "=l"(d) : "l"(a), "l"(b));
    return d;
}
__device__ __forceinline__ u64 pack2(float lo, float hi) {
    u64 d;
    asm("mov.b64 %0, {%1, %2};" : "=l"(d) : "f"(lo), "f"(hi));
    return d;
}
// 256-bit input load, non-coherent, L2 evict-last (keep shared input hot).
__device__ __forceinline__ void ldg256_el(const void* p, u64* v) {
    asm volatile("ld.global.nc.L2::evict_last.v4.b64 {%0, %1, %2, %3}, [%4];"
                 : "=l"(v[0]), "=l"(v[1]), "=l"(v[2]), "=l"(v[3])
                 : "l"(p));
}
// 256-bit store, evict-first.
__device__ __forceinline__ void stg256_cs(void* p, const u64* v) {
    asm volatile("st.global.cs.v4.b64 [%0], {%1, %2, %3, %4};"
                 :: "l"(p), "l"(v[0]), "l"(v[1]), "l"(v[2]), "l"(v[3])
                 : "memory");
}

__global__ __launch_bounds__(128, 2)
void laplace_kernel(const float* __restrict__ inp, float* __restrict__ out) {
    const int tid  = threadIdx.x;
    const int lane = tid & 31;       // 32B piece within a 1KB row
    const int iq   = tid >> 5;       // 0..3 -> which triple of the 12 i's
    const int ib   = blockIdx.x;     // 0..8
    const int chunk = blockIdx.y;    // 0..31

    // Per-i constants in double precision (matches reference ~1e-7).
    u64 e2[KI], d2[KI];
    const double c = pow(20.0, 1.0 / 99.0) - 1.0;
    #pragma unroll
    for (int k = 0; k < KI; k++) {
        int i = ib * GI + iq * KI + k;
        double tau = pow(1.0 + c, (double)(i - 4));
        double s   = 4.0 / tau;
        double ed  = exp(-s);
        float ef = (float)ed;
        float df = (float)((1.0 - ed) / s);
        e2[k] = pack2(ef, ef);
        d2[k] = pack2(df, df);
    }

    const int t_start = chunk * CHUNK;
    const int wneed   = WTAB[ib];                             // 8..56, mult of 8
    const int warm    = (t_start < wneed) ? t_start : wneed;  // 0 or wneed
    const int t0      = t_start - warm;
    const int steps   = warm + CHUNK;

    const char* __restrict__ ipb = reinterpret_cast<const char*>(inp)
                                   + (size_t)t0 * ROWB + lane * 32;

    // Scaled states: st' = e*st' + x;  out = dcy * st'.  float8 per state.
    u64 st[KI][4];
    #pragma unroll
    for (int k = 0; k < KI; k++)
        #pragma unroll
        for (int q = 0; q < 4; q++) st[k][q] = 0ull;

    // Prime the register pipeline (PF rows of 32B each).
    u64 pf[PF][4];
    #pragma unroll
    for (int j = 0; j < PF; j++) ldg256_el(ipb + (size_t)j * ROWB, pf[j]);

    // ---- warm-up (no stores); warm is 0 or a multiple of PF ----
    for (int tb = 0; tb < warm; tb += PF) {
        #pragma unroll
        for (int j = 0; j < PF; j++) {
            const int t = tb + j;
            u64 x[4];
            #pragma unroll
            for (int q = 0; q < 4; q++) x[q] = pf[j][q];
            const int tn = t + PF;
            if (tn < steps) ldg256_el(ipb + (size_t)tn * ROWB, pf[j]);
            #pragma unroll
            for (int k = 0; k < KI; k++)
                #pragma unroll
                for (int q = 0; q < 4; q++)
                    st[k][q] = fma2(e2[k], st[k][q], x[q]);
        }
    }

    // ---- main: CHUNK=64 stored rows, 3 STG.256.cs per thread per row ----
    char* opb = reinterpret_cast<char*>(out)
              + ((size_t)t_start * NS + (size_t)(ib * GI + iq * KI)) * ROWB
              + lane * 32;
    for (int tb = 0; tb < CHUNK; tb += PF) {
        #pragma unroll
        for (int j = 0; j < PF; j++) {
            const int t = warm + tb + j;
            u64 x[4];
            #pragma unroll
            for (int q = 0; q < 4; q++) x[q] = pf[j][q];
            const int tn = t + PF;
            if (tn < steps) ldg256_el(ipb + (size_t)tn * ROWB, pf[j]);
            #pragma unroll
            for (int k = 0; k < KI; k++) {
                u64 o[4];
                #pragma unroll
                for (int q = 0; q < 4; q++) {
                    st[k][q] = fma2(e2[k], st[k][q], x[q]);
                    o[q]     = mul2(d2[k], st[k][q]);
                }
                stg256_cs(opb + (size_t)k * ROWB, o);
            }
            opb += (size_t)NS * ROWB;
        }
    }
}

extern "C" void kernel_launch(void* const* d_in, const int* in_sizes, int n_in,
                              void* d_out, int out_size) {
    const float* inp = (const float*)d_in[0];
    float* out       = (float*)d_out;
    dim3 grid(NIB, NCHUNK);   // 9 x 32 = 288 blocks
    laplace_kernel<<<grid, 128>>>(inp, out);
}